// round 16
// baseline (speedup 1.0000x reference)
#include <cuda_runtime.h>
#include <cuda_fp16.h>
#include <math.h>
#include <stdint.h>

#define N_NODES 50000
#define N_EDGES 1600000
#define IN_DIM  1024
#define HID_DIM 2048
#define OUT_DIM 3
#define BN_EPS  1e-5f
#define SCAN_BLOCKS ((N_NODES + 255) / 256)   // 196

// ---------------- scratch ----------------
__device__ int   g_outdeg[N_NODES];
__device__ int   g_indeg[N_NODES];
__device__ float g_outnorm[N_NODES];
__device__ float g_innorm[N_NODES];
__device__ int   g_off[N_NODES + 1];
__device__ int   g_pos[N_NODES];
__device__ int   g_blocksum[SCAN_BLOCKS];
__device__ int   g_col[N_EDGES];
__device__ __half g_Xh[(size_t)N_NODES * IN_DIM];   // 100 MB: fp16(out_norm * X)
__device__ __half g_Ah[(size_t)N_NODES * IN_DIM];   // 100 MB: fp16 aggregated A
__device__ __half g_Wt[(size_t)HID_DIM * IN_DIM];   // 4 MB  [N,K] fp16 W1^T
__device__ __half g_hh[(size_t)N_NODES * HID_DIM];  // 205 MB fp16 relu(h)
__device__ float g_bnsum[HID_DIM];
__device__ float g_bnsq[HID_DIM];
__device__ float g_g[(size_t)N_NODES * OUT_DIM];

// ---------------- PTX helpers (sm_80-compatible only) ----------------
__device__ __forceinline__ uint32_t smem_u32(const void* p) {
    uint32_t a;
    asm("{ .reg .u64 t; cvta.to.shared.u64 t, %1; cvt.u32.u64 %0, t; }" : "=r"(a) : "l"(p));
    return a;
}
__device__ __forceinline__ void cp_async16(uint32_t dst, const void* src, int srcsize) {
    asm volatile("cp.async.cg.shared.global [%0], [%1], 16, %2;\n"
                 :: "r"(dst), "l"(src), "r"(srcsize));
}
#define CP_COMMIT() asm volatile("cp.async.commit_group;\n" ::: "memory")
template<int N> __device__ __forceinline__ void cp_wait() {
    asm volatile("cp.async.wait_group %0;\n" :: "n"(N) : "memory");
}
__device__ __forceinline__ void ldsm4(uint32_t* r, uint32_t addr) {
    asm volatile("ldmatrix.sync.aligned.m8n8.x4.shared.b16 {%0,%1,%2,%3}, [%4];"
                 : "=r"(r[0]), "=r"(r[1]), "=r"(r[2]), "=r"(r[3]) : "r"(addr));
}
__device__ __forceinline__ void mma16816(float* d, const uint32_t* a, uint32_t b0, uint32_t b1) {
    asm volatile(
        "mma.sync.aligned.m16n8k16.row.col.f32.f16.f16.f32 "
        "{%0,%1,%2,%3}, {%4,%5,%6,%7}, {%8,%9}, {%0,%1,%2,%3};"
        : "+f"(d[0]), "+f"(d[1]), "+f"(d[2]), "+f"(d[3])
        : "r"(a[0]), "r"(a[1]), "r"(a[2]), "r"(a[3]), "r"(b0), "r"(b1));
}

// ---------------- small kernels ----------------
__global__ void k_zero() {
    int i = blockIdx.x * blockDim.x + threadIdx.x;
    if (i < N_NODES) { g_outdeg[i] = 0; g_indeg[i] = 0; }
    if (i < HID_DIM) { g_bnsum[i] = 0.f; g_bnsq[i] = 0.f; }
}

// degree count, 4 edges per thread (vectorized reads)
__global__ void k_deg(const int* __restrict__ src, const int* __restrict__ dst) {
    int e4 = blockIdx.x * blockDim.x + threadIdx.x;
    if (e4 < N_EDGES / 4) {
        int4 s = *(const int4*)&src[e4 * 4];
        int4 d = *(const int4*)&dst[e4 * 4];
        atomicAdd(&g_outdeg[s.x], 1); atomicAdd(&g_outdeg[s.y], 1);
        atomicAdd(&g_outdeg[s.z], 1); atomicAdd(&g_outdeg[s.w], 1);
        atomicAdd(&g_indeg[d.x], 1); atomicAdd(&g_indeg[d.y], 1);
        atomicAdd(&g_indeg[d.z], 1); atomicAdd(&g_indeg[d.w], 1);
    }
}

// scan phase 1 + degree norms (fused)
__global__ void k_scan1() {
    __shared__ int sdata[256];
    int t = threadIdx.x;
    int i = blockIdx.x * 256 + t;
    int x = (i < N_NODES) ? g_indeg[i] : 0;
    if (i < N_NODES) {
        int od = g_outdeg[i]; if (od < 1) od = 1;
        int id = x; if (id < 1) id = 1;
        g_outnorm[i] = rsqrtf((float)od);
        g_innorm[i]  = rsqrtf((float)id);
    }
    sdata[t] = x;
    __syncthreads();
    #pragma unroll
    for (int ofs = 1; ofs < 256; ofs <<= 1) {
        int v = (t >= ofs) ? sdata[t - ofs] : 0;
        __syncthreads();
        sdata[t] += v;
        __syncthreads();
    }
    if (i < N_NODES) g_off[i] = sdata[t] - x;
    if (t == 255) g_blocksum[blockIdx.x] = sdata[255];
}

__global__ void k_scan2() {
    __shared__ int sdata[256];
    int t = threadIdx.x;
    int x = (t < SCAN_BLOCKS) ? g_blocksum[t] : 0;
    sdata[t] = x;
    __syncthreads();
    #pragma unroll
    for (int ofs = 1; ofs < 256; ofs <<= 1) {
        int v = (t >= ofs) ? sdata[t - ofs] : 0;
        __syncthreads();
        sdata[t] += v;
        __syncthreads();
    }
    if (t < SCAN_BLOCKS) g_blocksum[t] = sdata[t] - x;
}

__global__ void k_scan3() {
    int t = threadIdx.x;
    int i = blockIdx.x * 256 + t;
    if (i < N_NODES) {
        int v = g_off[i] + g_blocksum[blockIdx.x];
        g_off[i] = v;
        g_pos[i] = v;
    }
    if (i == 0) g_off[N_NODES] = N_EDGES;
}

__global__ void k_fill(const int* __restrict__ src, const int* __restrict__ dst) {
    int e = blockIdx.x * blockDim.x + threadIdx.x;
    if (e < N_EDGES) {
        int p = atomicAdd(&g_pos[dst[e]], 1);
        g_col[p] = src[e];
    }
}

// fused: W transpose->fp16  +  Xh = fp16(out_norm * X)
// range [0, WBLOCKS): transw; [WBLOCKS, WBLOCKS+PBLOCKS): prep
#define WBLOCKS ((IN_DIM * HID_DIM + 255) / 256)            // 8192
#define PBLOCKS ((N_NODES * (IN_DIM / 4) + 255) / 256)      // 50000
__global__ void k_wxprep(const float* __restrict__ W1, const float* __restrict__ X) {
    int b = blockIdx.x;
    if (b < WBLOCKS) {
        int idx = b * 256 + threadIdx.x;
        if (idx < IN_DIM * HID_DIM) {
            int k = idx / HID_DIM, n = idx % HID_DIM;
            g_Wt[(size_t)n * IN_DIM + k] = __float2half_rn(W1[idx]);
        }
    } else {
        int idx = (b - WBLOCKS) * 256 + threadIdx.x;
        if (idx < N_NODES * (IN_DIM / 4)) {
            int row = idx >> 8;
            float w = g_outnorm[row];
            float4 v = *(const float4*)&X[(size_t)idx * 4];
            __half2* d = (__half2*)&g_Xh[(size_t)idx * 4];
            d[0] = __floats2half2_rn(v.x * w, v.y * w);
            d[1] = __floats2half2_rn(v.z * w, v.w * w);
        }
    }
}

// SpMM1: Ah[row] = fp16( in_norm[row] * sum Xh[s] )
// 128 threads; each thread owns 8 halves (16B); 4-edge unroll for MLP.
__global__ void __launch_bounds__(128) k_spmm1() {
    int row = blockIdx.x;
    int t = threadIdx.x;
    int beg = g_off[row], end = g_off[row + 1];
    size_t coff = (size_t)t * 8;
    float a0 = 0.f, a1 = 0.f, a2 = 0.f, a3 = 0.f;
    float a4 = 0.f, a5 = 0.f, a6 = 0.f, a7 = 0.f;
    int j = beg;
    for (; j + 3 < end; j += 4) {
        int s0 = g_col[j];
        int s1 = g_col[j + 1];
        int s2 = g_col[j + 2];
        int s3 = g_col[j + 3];
        uint4 u0 = *(const uint4*)&g_Xh[(size_t)s0 * IN_DIM + coff];
        uint4 u1 = *(const uint4*)&g_Xh[(size_t)s1 * IN_DIM + coff];
        uint4 u2 = *(const uint4*)&g_Xh[(size_t)s2 * IN_DIM + coff];
        uint4 u3 = *(const uint4*)&g_Xh[(size_t)s3 * IN_DIM + coff];
        float2 f;
        f = __half22float2(*(__half2*)&u0.x); a0 += f.x; a1 += f.y;
        f = __half22float2(*(__half2*)&u0.y); a2 += f.x; a3 += f.y;
        f = __half22float2(*(__half2*)&u0.z); a4 += f.x; a5 += f.y;
        f = __half22float2(*(__half2*)&u0.w); a6 += f.x; a7 += f.y;
        f = __half22float2(*(__half2*)&u1.x); a0 += f.x; a1 += f.y;
        f = __half22float2(*(__half2*)&u1.y); a2 += f.x; a3 += f.y;
        f = __half22float2(*(__half2*)&u1.z); a4 += f.x; a5 += f.y;
        f = __half22float2(*(__half2*)&u1.w); a6 += f.x; a7 += f.y;
        f = __half22float2(*(__half2*)&u2.x); a0 += f.x; a1 += f.y;
        f = __half22float2(*(__half2*)&u2.y); a2 += f.x; a3 += f.y;
        f = __half22float2(*(__half2*)&u2.z); a4 += f.x; a5 += f.y;
        f = __half22float2(*(__half2*)&u2.w); a6 += f.x; a7 += f.y;
        f = __half22float2(*(__half2*)&u3.x); a0 += f.x; a1 += f.y;
        f = __half22float2(*(__half2*)&u3.y); a2 += f.x; a3 += f.y;
        f = __half22float2(*(__half2*)&u3.z); a4 += f.x; a5 += f.y;
        f = __half22float2(*(__half2*)&u3.w); a6 += f.x; a7 += f.y;
    }
    for (; j < end; j++) {
        int s0 = g_col[j];
        uint4 u0 = *(const uint4*)&g_Xh[(size_t)s0 * IN_DIM + coff];
        float2 f;
        f = __half22float2(*(__half2*)&u0.x); a0 += f.x; a1 += f.y;
        f = __half22float2(*(__half2*)&u0.y); a2 += f.x; a3 += f.y;
        f = __half22float2(*(__half2*)&u0.z); a4 += f.x; a5 += f.y;
        f = __half22float2(*(__half2*)&u0.w); a6 += f.x; a7 += f.y;
    }
    float inw = g_innorm[row];
    uint4 o;
    __half2 h;
    h = __floats2half2_rn(a0 * inw, a1 * inw); o.x = *(uint32_t*)&h;
    h = __floats2half2_rn(a2 * inw, a3 * inw); o.y = *(uint32_t*)&h;
    h = __floats2half2_rn(a4 * inw, a5 * inw); o.z = *(uint32_t*)&h;
    h = __floats2half2_rn(a6 * inw, a7 * inw); o.w = *(uint32_t*)&h;
    *(uint4*)&g_Ah[(size_t)row * IN_DIM + coff] = o;
}

// ---------------- mma.sync GEMM1, single-term fp16 ----------------
#define GBM 128
#define GBN 128
#define STAGE_B 32768           // A 16KB + B 16KB
#define N_ITERS 16              // 16 K-chunks of 64
#define GDYN (3 * STAGE_B)

__device__ __forceinline__ void g_load_stage(uint32_t sbase, int m0, int n0, int k0, int tid) {
    #pragma unroll
    for (int i = 0; i < 4; i++) {            // A: 128 rows x 64 fp16
        int cid = tid + i * 256;
        int r = cid >> 3, c = cid & 7;
        int gm = m0 + r;
        int ok = (gm < N_NODES);
        const char* src = (const char*)(g_Ah + (size_t)(ok ? gm : 0) * IN_DIM + k0) + c * 16;
        uint32_t dst = sbase + r * 128 + ((c ^ (r & 7)) * 16);
        cp_async16(dst, src, ok ? 16 : 0);
    }
    #pragma unroll
    for (int i = 0; i < 4; i++) {            // B: 128 n-rows x 64 fp16
        int cid = tid + i * 256;
        int r = cid >> 3, c = cid & 7;
        const char* src = (const char*)(g_Wt + (size_t)(n0 + r) * IN_DIM + k0) + c * 16;
        uint32_t dst = sbase + 16384 + r * 128 + ((c ^ (r & 7)) * 16);
        cp_async16(dst, src, 16);
    }
}

__global__ void __launch_bounds__(256, 2) k_gemm_mma(const float* __restrict__ bias) {
    extern __shared__ char smem[];
    uint32_t sb = smem_u32(smem);
    int tid = threadIdx.x;
    int wid = tid >> 5;
    int lane = tid & 31;
    int n0 = blockIdx.x * GBN;
    int m0 = blockIdx.y * GBM;
    int wm = (wid >> 1) * 32;
    int wn = (wid & 1) * 64;

    float acc[2][8][4];
    #pragma unroll
    for (int i = 0; i < 2; i++)
        #pragma unroll
        for (int j = 0; j < 8; j++)
            #pragma unroll
            for (int q = 0; q < 4; q++) acc[i][j][q] = 0.f;

    g_load_stage(sb + 0 * STAGE_B, m0, n0, 0, tid);
    CP_COMMIT();
    g_load_stage(sb + 1 * STAGE_B, m0, n0, 64, tid);
    CP_COMMIT();

    for (int it = 0; it < N_ITERS; it++) {
        cp_wait<1>();
        __syncthreads();
        int nx = it + 2;
        if (nx < N_ITERS)
            g_load_stage(sb + (nx % 3) * STAGE_B, m0, n0, nx * 64, tid);
        CP_COMMIT();

        uint32_t bufA = sb + (it % 3) * STAGE_B;
        uint32_t bufB = bufA + 16384;
        #pragma unroll
        for (int ks = 0; ks < 4; ks++) {
            uint32_t a[2][4], b[4][4];
            #pragma unroll
            for (int am = 0; am < 2; am++) {
                int r = wm + am * 16 + (lane & 15);
                int ch = ks * 2 + (lane >> 4);
                ldsm4(a[am], bufA + r * 128 + ((ch ^ (r & 7)) * 16));
            }
            #pragma unroll
            for (int bp = 0; bp < 4; bp++) {
                int r = wn + bp * 16 + (lane & 15);
                int ch = ks * 2 + (lane >> 4);
                ldsm4(b[bp], bufB + r * 128 + ((ch ^ (r & 7)) * 16));
            }
            #pragma unroll
            for (int am = 0; am < 2; am++)
                #pragma unroll
                for (int bp = 0; bp < 4; bp++) {
                    mma16816(acc[am][bp * 2 + 0], a[am], b[bp][0], b[bp][2]);
                    mma16816(acc[am][bp * 2 + 1], a[am], b[bp][1], b[bp][3]);
                }
        }
        __syncthreads();
    }

    // epilogue: +bias, relu, fp16 store, fused BN partial sums (fp32 values)
    #pragma unroll
    for (int bn8 = 0; bn8 < 8; bn8++) {
        int col = n0 + wn + bn8 * 8 + (lane & 3) * 2;
        float bv0 = __ldg(&bias[col]);
        float bv1 = __ldg(&bias[col + 1]);
        float s0 = 0.f, s1 = 0.f, q0 = 0.f, q1 = 0.f;
        #pragma unroll
        for (int am = 0; am < 2; am++) {
            int row0 = m0 + wm + am * 16 + (lane >> 2);
            if (row0 < N_NODES) {
                float ox = fmaxf(acc[am][bn8][0] + bv0, 0.f);
                float oy = fmaxf(acc[am][bn8][1] + bv1, 0.f);
                *(__half2*)&g_hh[(size_t)row0 * HID_DIM + col] = __floats2half2_rn(ox, oy);
                s0 += ox; q0 += ox * ox;
                s1 += oy; q1 += oy * oy;
            }
            int row1 = row0 + 8;
            if (row1 < N_NODES) {
                float ox = fmaxf(acc[am][bn8][2] + bv0, 0.f);
                float oy = fmaxf(acc[am][bn8][3] + bv1, 0.f);
                *(__half2*)&g_hh[(size_t)row1 * HID_DIM + col] = __floats2half2_rn(ox, oy);
                s0 += ox; q0 += ox * ox;
                s1 += oy; q1 += oy * oy;
            }
        }
        #pragma unroll
        for (int o = 4; o < 32; o <<= 1) {
            s0 += __shfl_xor_sync(0xffffffffu, s0, o);
            s1 += __shfl_xor_sync(0xffffffffu, s1, o);
            q0 += __shfl_xor_sync(0xffffffffu, q0, o);
            q1 += __shfl_xor_sync(0xffffffffu, q1, o);
        }
        if (lane < 4) {
            atomicAdd(&g_bnsum[col], s0);
            atomicAdd(&g_bnsum[col + 1], s1);
            atomicAdd(&g_bnsq[col], q0);
            atomicAdd(&g_bnsq[col + 1], q1);
        }
    }
}

// projection: g[i] = (BN(hh[i]) * out_norm[i]) @ Wout ; mean/rstd computed inline
__global__ __launch_bounds__(256) void k_proj(const float* __restrict__ Wout) {
    __shared__ float sW[HID_DIM * OUT_DIM];
    __shared__ float sMean[HID_DIM];
    __shared__ float sRstd[HID_DIM];
    int tid = threadIdx.x;
    for (int i = tid; i < HID_DIM * OUT_DIM; i += 256) sW[i] = Wout[i];
    for (int i = tid; i < HID_DIM; i += 256) {
        float m = g_bnsum[i] * (1.f / N_NODES);
        float var = g_bnsq[i] * (1.f / N_NODES) - m * m;
        if (var < 0.f) var = 0.f;
        sMean[i] = m;
        sRstd[i] = rsqrtf(var + BN_EPS);
    }
    __syncthreads();
    int warp = tid >> 5;
    int lane = tid & 31;
    int row = blockIdx.x * 8 + warp;
    if (row >= N_NODES) return;
    const __half* hr = &g_hh[(size_t)row * HID_DIM];
    float p0 = 0, p1 = 0, p2 = 0;
    #pragma unroll 4
    for (int i = 0; i < HID_DIM / 64; i++) {
        int c = lane * 2 + i * 64;
        float2 f = __half22float2(*(const __half2*)&hr[c]);
        float hn0 = (f.x - sMean[c]) * sRstd[c];
        float hn1 = (f.y - sMean[c + 1]) * sRstd[c + 1];
        p0 += hn0 * sW[c * 3 + 0] + hn1 * sW[c * 3 + 3];
        p1 += hn0 * sW[c * 3 + 1] + hn1 * sW[c * 3 + 4];
        p2 += hn0 * sW[c * 3 + 2] + hn1 * sW[c * 3 + 5];
    }
    #pragma unroll
    for (int o = 16; o > 0; o >>= 1) {
        p0 += __shfl_xor_sync(0xffffffffu, p0, o);
        p1 += __shfl_xor_sync(0xffffffffu, p1, o);
        p2 += __shfl_xor_sync(0xffffffffu, p2, o);
    }
    if (lane == 0) {
        float on = g_outnorm[row];
        g_g[row * 3 + 0] = p0 * on;
        g_g[row * 3 + 1] = p1 * on;
        g_g[row * 3 + 2] = p2 * on;
    }
}

// SpMM2 (dim 3) + softmax
__global__ __launch_bounds__(256) void k_spmm2(const float* __restrict__ bout,
                                               float* __restrict__ out) {
    int tid = threadIdx.x;
    int warp = tid >> 5;
    int lane = tid & 31;
    int row = blockIdx.x * 8 + warp;
    if (row >= N_NODES) return;
    int beg = g_off[row], end = g_off[row + 1];
    float a0 = 0, a1 = 0, a2 = 0;
    for (int j = beg + lane; j < end; j += 32) {
        int s = g_col[j];
        a0 += g_g[s * 3 + 0];
        a1 += g_g[s * 3 + 1];
        a2 += g_g[s * 3 + 2];
    }
    #pragma unroll
    for (int o = 16; o > 0; o >>= 1) {
        a0 += __shfl_xor_sync(0xffffffffu, a0, o);
        a1 += __shfl_xor_sync(0xffffffffu, a1, o);
        a2 += __shfl_xor_sync(0xffffffffu, a2, o);
    }
    if (lane == 0) {
        float inw = g_innorm[row];
        float v0 = a0 * inw + bout[0];
        float v1 = a1 * inw + bout[1];
        float v2 = a2 * inw + bout[2];
        float m = fmaxf(v0, fmaxf(v1, v2));
        float e0 = __expf(v0 - m), e1 = __expf(v1 - m), e2 = __expf(v2 - m);
        float inv = 1.f / (e0 + e1 + e2);
        out[row * 3 + 0] = e0 * inv;
        out[row * 3 + 1] = e1 * inv;
        out[row * 3 + 2] = e2 * inv;
    }
}

// ---------------- launch ----------------
extern "C" void kernel_launch(void* const* d_in, const int* in_sizes, int n_in,
                              void* d_out, int out_size) {
    const float* in_feat = (const float*)d_in[0];
    const int*   src     = (const int*)d_in[1];
    const int*   dst     = (const int*)d_in[2];
    const float* W1      = (const float*)d_in[3];
    const float* b1      = (const float*)d_in[4];
    const float* Wout    = (const float*)d_in[5];
    const float* bout    = (const float*)d_in[6];
    float* out = (float*)d_out;

    cudaFuncSetAttribute(k_gemm_mma, cudaFuncAttributeMaxDynamicSharedMemorySize, GDYN);

    k_zero<<<(N_NODES + 255) / 256, 256>>>();
    k_deg<<<(N_EDGES / 4 + 255) / 256, 256>>>(src, dst);
    k_scan1<<<SCAN_BLOCKS, 256>>>();
    k_scan2<<<1, 256>>>();
    k_scan3<<<SCAN_BLOCKS, 256>>>();
    k_fill<<<(N_EDGES + 255) / 256, 256>>>(src, dst);
    k_wxprep<<<WBLOCKS + PBLOCKS, 256>>>(W1, in_feat);
    k_spmm1<<<N_NODES, 128>>>();
    dim3 gg(HID_DIM / GBN, (N_NODES + GBM - 1) / GBM);
    k_gemm_mma<<<gg, 256, GDYN>>>(b1);
    k_proj<<<(N_NODES + 7) / 8, 256>>>(Wout);
    k_spmm2<<<(N_NODES + 7) / 8, 256>>>(bout, out);
}